// round 9
// baseline (speedup 1.0000x reference)
#include <cuda_runtime.h>
#include <cuda_fp16.h>
#include <stdint.h>

#define N_NODES 50000
#define N_EDGES 1000000
#define F_IN  64
#define F_HID 64
#define F_OUT 32

// ---------------- scratch (device globals: allocation-free rule) ----------------
// NOTE: g_cnt and g_base rely on zero-init at module load; every launch re-zeroes
// them in k_agg2's prologue-zero step, so each call starts from the same state.
__device__ __align__(16) __half g_hs1h[N_NODES * F_HID];  // fp16 X@W1 (unscaled)
__device__ __align__(16) __half g_hs2h[N_NODES * F_OUT];  // fp16 x2@W2 (unscaled)
__device__ float g_dinv[N_NODES];       // rsqrt(deg), deg = cnt+1
__device__ int g_cnt   [N_NODES];       // zeroed at tail of every launch
__device__ int g_rowptr[N_NODES];       // CSR start (blocks placed by atomic base)
__device__ int g_rowend[N_NODES];       // CSR end
__device__ int g_cursor[N_NODES];
__device__ int g_csrsrc[N_EDGES];
__device__ int g_base;                  // global CSR allocation counter

// ---------------- hist: 4 edges/thread, int4 loads (indices are int32) ----------------
__global__ void k_hist(const int* __restrict__ ei) {
    int i = blockIdx.x * blockDim.x + threadIdx.x;   // quad index
    if (4 * i >= N_EDGES) return;
    int4 v = ((const int4*)(ei + N_EDGES))[i];       // dst half
    atomicAdd(&g_cnt[v.x], 1);
    atomicAdd(&g_cnt[v.y], 1);
    atomicAdd(&g_cnt[v.z], 1);
    atomicAdd(&g_cnt[v.w], 1);
}

// ---------------- rowptr: block-local scan + atomic block base + dinv ----------------
// Blocks get bases in atomic arrival order -> rowptr is NOT globally monotonic,
// which is fine: [rowptr[i], rowend[i]) is a valid private range per node.
__global__ void __launch_bounds__(256) k_rowptr() {
    __shared__ int s[256];
    __shared__ int sbase;
    int t = threadIdx.x;
    int i = blockIdx.x * 256 + t;
    int c = (i < N_NODES) ? g_cnt[i] : 0;
    s[t] = c;
    __syncthreads();
    #pragma unroll
    for (int off = 1; off < 256; off <<= 1) {        // inclusive scan
        int v = (t >= off) ? s[t - off] : 0;
        __syncthreads();
        s[t] += v;
        __syncthreads();
    }
    if (t == 255) sbase = atomicAdd(&g_base, s[255]);
    __syncthreads();
    int excl = sbase + s[t] - c;
    if (i < N_NODES) {
        g_rowptr[i] = excl;
        g_rowend[i] = excl + c;
        g_cursor[i] = excl;
        g_dinv[i]   = rsqrtf((float)(c + 1));
    }
}

// ---------------- permute: 4 edges/thread ----------------
__global__ void k_permute(const int* __restrict__ ei) {
    int i = blockIdx.x * blockDim.x + threadIdx.x;   // quad index
    if (4 * i >= N_EDGES) return;
    int4 sv = ((const int4*)ei)[i];                  // src half
    int4 dv = ((const int4*)(ei + N_EDGES))[i];      // dst half
    g_csrsrc[atomicAdd(&g_cursor[dv.x], 1)] = sv.x;
    g_csrsrc[atomicAdd(&g_cursor[dv.y], 1)] = sv.y;
    g_csrsrc[atomicAdd(&g_cursor[dv.z], 1)] = sv.z;
    g_csrsrc[atomicAdd(&g_cursor[dv.w], 1)] = sv.w;
}

// ---------------- GEMM1: hs1h = fp16( X @ W1 )  (unscaled; independent of CSR) ----------------
#define SWZ1(r, k) ((k) ^ ((((r) >> 3) & 3) << 3))
__global__ void __launch_bounds__(128) k_gemm1(const float* __restrict__ x,
                                               const float* __restrict__ W) {
    __shared__ float Xs[128][64];            // 32 KB (swizzled k)
    __shared__ float Ws[64][64];             // 16 KB
    int t = threadIdx.x;
    int row0 = blockIdx.x * 128;

    for (int i = t; i < 64 * 16; i += 128) {
        int k = i >> 4, c = (i & 15) * 4;
        *(float4*)&Ws[k][c] = *(const float4*)(W + k * 64 + c);
    }
    {
        int rl = t >> 4;
        int kg = (t & 15) * 4;
        #pragma unroll
        for (int i = 0; i < 16; i++) {
            int r = rl + i * 8;
            int gr = row0 + r;
            float4 v = make_float4(0.f, 0.f, 0.f, 0.f);
            if (gr < N_NODES) v = *(const float4*)(x + gr * 64 + kg);
            *(float4*)&Xs[r][SWZ1(r, kg)] = v;
        }
    }
    __syncthreads();

    int tx = t & 7, ty = t >> 3;
    int cb = tx * 8, rb = ty * 8;
    float acc[8][8];
    #pragma unroll
    for (int i = 0; i < 8; i++)
        #pragma unroll
        for (int j = 0; j < 8; j++) acc[i][j] = 0.f;

    #pragma unroll
    for (int k = 0; k < 64; k++) {
        float wv[8];
        *(float4*)&wv[0] = *(float4*)&Ws[k][cb];
        *(float4*)&wv[4] = *(float4*)&Ws[k][cb + 4];
        float xv[8];
        #pragma unroll
        for (int i = 0; i < 8; i++) xv[i] = Xs[rb + i][SWZ1(rb + i, k)];
        #pragma unroll
        for (int i = 0; i < 8; i++)
            #pragma unroll
            for (int j = 0; j < 8; j++) acc[i][j] = fmaf(xv[i], wv[j], acc[i][j]);
    }

    #pragma unroll
    for (int i = 0; i < 8; i++) {
        int r = row0 + rb + i;
        if (r < N_NODES) {
            __half2 h[4];
            #pragma unroll
            for (int j = 0; j < 4; j++)
                h[j] = __floats2half2_rn(acc[i][2*j], acc[i][2*j+1]);
            *(uint4*)(g_hs1h + r * 64 + cb) = *(uint4*)h;
        }
    }
}

// ---------------- fused agg1 + GEMM2 ----------------
// Block = 128 nodes, 256 threads.
// Phase A: 8 warps x 16 nodes; warp aggregates dinv-weighted hs1 rows (lane owns
//          half2 col), applies relu(.+b1), writes x2 row into smem.
// Phase B: 128x32 GEMM (x2 @ W2) with 4x4 micro-tile -> hs2h (unscaled fp16).
__global__ void __launch_bounds__(256) k_agg1gemm2(const float* __restrict__ b1,
                                                   const float* __restrict__ W2) {
    __shared__ float Xs[128][65];            // 33.3 KB
    __shared__ float Ws[64][32];             // 8 KB
    int t = threadIdx.x;
    int row0 = blockIdx.x * 128;
    int wid = t >> 5, lane = t & 31;

    for (int i = t; i < 64 * 8; i += 256) {  // load W2 (512 float4)
        int k = i >> 3, c = (i & 7) * 4;
        *(float4*)&Ws[k][c] = *(const float4*)(W2 + k * 32 + c);
    }

    const __half2* hs = (const __half2*)g_hs1h;
    float bx = b1[2 * lane], by = b1[2 * lane + 1];

    #pragma unroll 1
    for (int ni = 0; ni < 16; ni++) {
        int r = wid * 16 + ni;               // 0..127
        int node = row0 + r;
        float2 o = make_float2(0.f, 0.f);
        if (node < N_NODES) {
            int e = g_rowptr[node], end = g_rowend[node];
            float dn = g_dinv[node];
            float2 f = __half22float2(hs[node * 32 + lane]);   // self-loop
            float2 acc = make_float2(f.x * dn, f.y * dn);
            for (; e + 4 <= end; e += 4) {
                int s0 = g_csrsrc[e + 0], s1 = g_csrsrc[e + 1];
                int s2 = g_csrsrc[e + 2], s3 = g_csrsrc[e + 3];
                float d0 = g_dinv[s0], d1 = g_dinv[s1], d2 = g_dinv[s2], d3 = g_dinv[s3];
                float2 f0 = __half22float2(hs[s0 * 32 + lane]);
                float2 f1 = __half22float2(hs[s1 * 32 + lane]);
                float2 f2 = __half22float2(hs[s2 * 32 + lane]);
                float2 f3 = __half22float2(hs[s3 * 32 + lane]);
                acc.x += f0.x * d0 + f1.x * d1 + f2.x * d2 + f3.x * d3;
                acc.y += f0.y * d0 + f1.y * d1 + f2.y * d2 + f3.y * d3;
            }
            for (; e < end; e++) {
                int s0 = g_csrsrc[e];
                float d0 = g_dinv[s0];
                float2 v = __half22float2(hs[s0 * 32 + lane]);
                acc.x += v.x * d0; acc.y += v.y * d0;
            }
            o.x = fmaxf(fmaf(acc.x, dn, bx), 0.f);
            o.y = fmaxf(fmaf(acc.y, dn, by), 0.f);
        }
        Xs[r][2 * lane]     = o.x;
        Xs[r][2 * lane + 1] = o.y;
    }
    __syncthreads();

    // Phase B: 256 threads, 4x4 micro-tile over 128x32
    int tx = t & 7, ty = t >> 3;             // 8 col-groups(4) x 32 row-groups(4)
    int cb = tx * 4, rb = ty * 4;
    float acc[4][4];
    #pragma unroll
    for (int i = 0; i < 4; i++)
        #pragma unroll
        for (int j = 0; j < 4; j++) acc[i][j] = 0.f;

    #pragma unroll
    for (int k = 0; k < 64; k++) {
        float wv[4];
        *(float4*)&wv[0] = *(float4*)&Ws[k][cb];
        float xv[4];
        #pragma unroll
        for (int i = 0; i < 4; i++) xv[i] = Xs[rb + i][k];
        #pragma unroll
        for (int i = 0; i < 4; i++)
            #pragma unroll
            for (int j = 0; j < 4; j++) acc[i][j] = fmaf(xv[i], wv[j], acc[i][j]);
    }

    #pragma unroll
    for (int i = 0; i < 4; i++) {
        int r = row0 + rb + i;
        if (r < N_NODES) {
            __half2 h[2];
            h[0] = __floats2half2_rn(acc[i][0], acc[i][1]);
            h[1] = __floats2half2_rn(acc[i][2], acc[i][3]);
            *(uint2*)(g_hs2h + r * 32 + cb) = *(uint2*)h;
        }
    }
}

// ---------------- agg2: out = dinv[n]*(dinv[n]*hs2[n] + sum dinv[s]*hs2[s]) + b2 ----------------
// Also re-zeroes g_cnt / g_base for the next launch (state invariant).
__global__ void __launch_bounds__(256) k_agg2(float* __restrict__ out,
                                              const float* __restrict__ b2) {
    int gtid = blockIdx.x * 256 + threadIdx.x;
    if (gtid < N_NODES) g_cnt[gtid] = 0;     // tail-zero for next launch
    if (gtid == 0) g_base = 0;

    int node = blockIdx.x * 8 + (threadIdx.x >> 5);
    if (node >= N_NODES) return;
    int lane = threadIdx.x & 31;
    int sub = lane >> 4;
    int c = lane & 15;
    const __half2* hs = (const __half2*)g_hs2h;

    int start = g_rowptr[node], end = g_rowend[node];
    float dn = g_dinv[node];
    float2 acc = make_float2(0.f, 0.f);
    if (sub == 0) {
        float2 f = __half22float2(hs[node * 16 + c]);       // self-loop
        acc.x = f.x * dn; acc.y = f.y * dn;
    }
    int e = start + sub;
    for (; e + 2 < end; e += 4) {            // reads e and e+2
        int s0 = g_csrsrc[e], s1 = g_csrsrc[e + 2];
        float d0 = g_dinv[s0], d1 = g_dinv[s1];
        float2 f0 = __half22float2(hs[s0 * 16 + c]);
        float2 f1 = __half22float2(hs[s1 * 16 + c]);
        acc.x += f0.x * d0 + f1.x * d1;
        acc.y += f0.y * d0 + f1.y * d1;
    }
    if (e < end) {
        int s0 = g_csrsrc[e];
        float d0 = g_dinv[s0];
        float2 f = __half22float2(hs[s0 * 16 + c]);
        acc.x += f.x * d0; acc.y += f.y * d0;
    }
    acc.x += __shfl_xor_sync(0xffffffffu, acc.x, 16);
    acc.y += __shfl_xor_sync(0xffffffffu, acc.y, 16);
    if (sub == 0) {
        float2 bb = *(const float2*)(b2 + 2 * c);
        float2 o = make_float2(fmaf(acc.x, dn, bb.x), fmaf(acc.y, dn, bb.y));
        *(float2*)(out + node * 32 + 2 * c) = o;
    }
}

// ---------------- side-stream resources (CPU objects, created once) ----------------
struct SideRes {
    cudaStream_t s;
    cudaEvent_t fork, join;
    SideRes() {
        cudaStreamCreateWithFlags(&s, cudaStreamNonBlocking);
        cudaEventCreateWithFlags(&fork, cudaEventDisableTiming);
        cudaEventCreateWithFlags(&join, cudaEventDisableTiming);
    }
};
static SideRes& side() { static SideRes r; return r; }

// ----------------------------------------------------------------
extern "C" void kernel_launch(void* const* d_in, const int* in_sizes, int n_in,
                              void* d_out, int out_size) {
    const float* x  = (const float*)d_in[0];
    const int*   ei = (const int*)d_in[1];   // int32 (established in R2/R3)
    const float* W1 = (const float*)d_in[2];
    const float* b1 = (const float*)d_in[3];
    const float* W2 = (const float*)d_in[4];
    const float* b2 = (const float*)d_in[5];

    SideRes& r = side();

    // gemm1 is edge-independent: run on side stream alongside CSR build
    cudaEventRecord(r.fork, (cudaStream_t)0);
    cudaStreamWaitEvent(r.s, r.fork, 0);
    k_gemm1<<<(N_NODES + 127) / 128, 128, 0, r.s>>>(x, W1);
    cudaEventRecord(r.join, r.s);

    k_hist   <<<(N_EDGES / 4 + 255) / 256, 256>>>(ei);
    k_rowptr <<<(N_NODES + 255) / 256, 256>>>();
    k_permute<<<(N_EDGES / 4 + 255) / 256, 256>>>(ei);

    cudaStreamWaitEvent((cudaStream_t)0, r.join, 0);
    k_agg1gemm2<<<(N_NODES + 127) / 128, 256>>>(b1, W2);
    k_agg2     <<<(N_NODES + 7) / 8, 256>>>((float*)d_out, b2);
}

// round 10
// speedup vs baseline: 1.3336x; 1.3336x over previous
#include <cuda_runtime.h>
#include <cuda_fp16.h>
#include <stdint.h>

#define N_NODES 50000
#define N_EDGES 1000000
#define F_IN  64
#define F_HID 64
#define F_OUT 32

// ---------------- scratch (device globals: allocation-free rule) ----------------
// g_cnt / g_base start zero (module load) and are re-zeroed at the tail of every
// launch (in k_agg2), so each call sees identical initial state.
__device__ __align__(16) __half g_hs1h[N_NODES * F_HID];  // fp16 dinv*(X@W1)
__device__ __align__(16) float  g_x2  [N_NODES * F_HID];  // relu(agg1 + b1)
__device__ __align__(16) __half g_hs2h[N_NODES * F_OUT];  // fp16 dinv*(x2@W2)
__device__ float g_dinv[N_NODES];       // rsqrt(deg), deg = cnt+1
__device__ int g_cnt   [N_NODES];
__device__ int g_rowptr[N_NODES];       // CSR start (atomic block base)
__device__ int g_rowend[N_NODES];       // CSR end
__device__ int g_cursor[N_NODES];
__device__ int g_csrsrc[N_EDGES];
__device__ int g_base;

// ---------------- hist: 4 edges/thread, int4 loads (indices are int32) ----------------
__global__ void k_hist(const int* __restrict__ ei) {
    int i = blockIdx.x * blockDim.x + threadIdx.x;   // quad index
    if (4 * i >= N_EDGES) return;
    int4 v = ((const int4*)(ei + N_EDGES))[i];       // dst half
    atomicAdd(&g_cnt[v.x], 1);
    atomicAdd(&g_cnt[v.y], 1);
    atomicAdd(&g_cnt[v.z], 1);
    atomicAdd(&g_cnt[v.w], 1);
}

// ---------------- rowptr: block scan + atomic block base + dinv ----------------
// Blocks get bases in atomic arrival order -> rowptr not globally monotonic;
// fine, since [rowptr[i], rowend[i]) is a private per-node range.
__global__ void __launch_bounds__(256) k_rowptr() {
    __shared__ int s[256];
    __shared__ int sbase;
    int t = threadIdx.x;
    int i = blockIdx.x * 256 + t;
    int c = (i < N_NODES) ? g_cnt[i] : 0;
    s[t] = c;
    __syncthreads();
    #pragma unroll
    for (int off = 1; off < 256; off <<= 1) {        // inclusive scan
        int v = (t >= off) ? s[t - off] : 0;
        __syncthreads();
        s[t] += v;
        __syncthreads();
    }
    if (t == 255) sbase = atomicAdd(&g_base, s[255]);
    __syncthreads();
    int excl = sbase + s[t] - c;
    if (i < N_NODES) {
        g_rowptr[i] = excl;
        g_rowend[i] = excl + c;
        g_cursor[i] = excl;
        g_dinv[i]   = rsqrtf((float)(c + 1));
    }
}

// ---------------- permute: 2 edges/thread ----------------
__global__ void k_permute(const int* __restrict__ ei) {
    int i = blockIdx.x * blockDim.x + threadIdx.x;   // pair index
    if (2 * i >= N_EDGES) return;
    int2 sv = ((const int2*)ei)[i];                  // src half
    int2 dv = ((const int2*)(ei + N_EDGES))[i];      // dst half
    g_csrsrc[atomicAdd(&g_cursor[dv.x], 1)] = sv.x;
    g_csrsrc[atomicAdd(&g_cursor[dv.y], 1)] = sv.y;
}

// ---------------- GEMM1: hs1h = fp16( dinv * (X @ W1) ) ----------------
#define SWZ1(r, k) ((k) ^ ((((r) >> 3) & 3) << 3))
__global__ void __launch_bounds__(128) k_gemm1(const float* __restrict__ x,
                                               const float* __restrict__ W) {
    __shared__ float Xs[128][64];            // 32 KB (swizzled k)
    __shared__ float Ws[64][64];             // 16 KB
    int t = threadIdx.x;
    int row0 = blockIdx.x * 128;

    for (int i = t; i < 64 * 16; i += 128) {
        int k = i >> 4, c = (i & 15) * 4;
        *(float4*)&Ws[k][c] = *(const float4*)(W + k * 64 + c);
    }
    {
        int rl = t >> 4;
        int kg = (t & 15) * 4;
        #pragma unroll
        for (int i = 0; i < 16; i++) {
            int r = rl + i * 8;
            int gr = row0 + r;
            float4 v = make_float4(0.f, 0.f, 0.f, 0.f);
            if (gr < N_NODES) v = *(const float4*)(x + gr * 64 + kg);
            *(float4*)&Xs[r][SWZ1(r, kg)] = v;
        }
    }
    __syncthreads();

    int tx = t & 7, ty = t >> 3;
    int cb = tx * 8, rb = ty * 8;
    float acc[8][8];
    #pragma unroll
    for (int i = 0; i < 8; i++)
        #pragma unroll
        for (int j = 0; j < 8; j++) acc[i][j] = 0.f;

    #pragma unroll
    for (int k = 0; k < 64; k++) {
        float wv[8];
        *(float4*)&wv[0] = *(float4*)&Ws[k][cb];
        *(float4*)&wv[4] = *(float4*)&Ws[k][cb + 4];
        float xv[8];
        #pragma unroll
        for (int i = 0; i < 8; i++) xv[i] = Xs[rb + i][SWZ1(rb + i, k)];
        #pragma unroll
        for (int i = 0; i < 8; i++)
            #pragma unroll
            for (int j = 0; j < 8; j++) acc[i][j] = fmaf(xv[i], wv[j], acc[i][j]);
    }

    #pragma unroll
    for (int i = 0; i < 8; i++) {
        int r = row0 + rb + i;
        if (r < N_NODES) {
            float s = g_dinv[r];
            __half2 h[4];
            #pragma unroll
            for (int j = 0; j < 4; j++)
                h[j] = __floats2half2_rn(acc[i][2*j] * s, acc[i][2*j+1] * s);
            *(uint4*)(g_hs1h + r * 64 + cb) = *(uint4*)h;
        }
    }
}

// ---------------- agg1: x2 = relu(dinv*(hs1[n] + sum hs1[src]) + b1) ----------------
// warp per node (6250 blocks x 8 warps); lane owns half2 column (128B row).
__global__ void __launch_bounds__(256) k_agg1(const float* __restrict__ b1) {
    int node = blockIdx.x * 8 + (threadIdx.x >> 5);
    if (node >= N_NODES) return;
    int lane = threadIdx.x & 31;
    const __half2* hs = (const __half2*)g_hs1h;

    int e = g_rowptr[node], end = g_rowend[node];
    float2 f = __half22float2(hs[node * 32 + lane]);        // self-loop
    float2 acc = make_float2(f.x, f.y);

    for (; e + 4 <= end; e += 4) {
        int s0 = g_csrsrc[e + 0], s1 = g_csrsrc[e + 1];
        int s2 = g_csrsrc[e + 2], s3 = g_csrsrc[e + 3];
        float2 f0 = __half22float2(hs[s0 * 32 + lane]);
        float2 f1 = __half22float2(hs[s1 * 32 + lane]);
        float2 f2 = __half22float2(hs[s2 * 32 + lane]);
        float2 f3 = __half22float2(hs[s3 * 32 + lane]);
        acc.x += (f0.x + f1.x) + (f2.x + f3.x);
        acc.y += (f0.y + f1.y) + (f2.y + f3.y);
    }
    for (; e < end; e++) {
        float2 v = __half22float2(hs[g_csrsrc[e] * 32 + lane]);
        acc.x += v.x; acc.y += v.y;
    }

    float s = g_dinv[node];
    float2 bb = *(const float2*)(b1 + 2 * lane);
    float2 o;
    o.x = fmaxf(fmaf(acc.x, s, bb.x), 0.f);
    o.y = fmaxf(fmaf(acc.y, s, bb.y), 0.f);
    *(float2*)(g_x2 + node * 64 + 2 * lane) = o;
}

// ---------------- GEMM2: hs2h = fp16( dinv * (x2 @ W2) ) ----------------
__global__ void __launch_bounds__(128) k_gemm2(const float* __restrict__ W) {
    __shared__ float Xs[128][65];
    __shared__ float Ws[64][32];
    int t = threadIdx.x;
    int row0 = blockIdx.x * 128;

    for (int i = t; i < 64 * 8; i += 128) {
        int k = i >> 3, c = (i & 7) * 4;
        *(float4*)&Ws[k][c] = *(const float4*)(W + k * 32 + c);
    }
    {
        int rl = t >> 4;
        int kg = (t & 15) * 4;
        #pragma unroll
        for (int i = 0; i < 16; i++) {
            int r = rl + i * 8;
            int gr = row0 + r;
            float4 v = make_float4(0.f, 0.f, 0.f, 0.f);
            if (gr < N_NODES) v = *(const float4*)(g_x2 + gr * 64 + kg);
            Xs[r][kg] = v.x; Xs[r][kg + 1] = v.y; Xs[r][kg + 2] = v.z; Xs[r][kg + 3] = v.w;
        }
    }
    __syncthreads();

    int tx = t & 7, ty = t >> 3;
    int cb = tx * 4, rb = ty * 8;
    float acc[8][4];
    #pragma unroll
    for (int i = 0; i < 8; i++)
        #pragma unroll
        for (int j = 0; j < 4; j++) acc[i][j] = 0.f;

    #pragma unroll
    for (int k = 0; k < 64; k++) {
        float wv[4];
        *(float4*)&wv[0] = *(float4*)&Ws[k][cb];
        float xv[8];
        #pragma unroll
        for (int i = 0; i < 8; i++) xv[i] = Xs[rb + i][k];
        #pragma unroll
        for (int i = 0; i < 8; i++)
            #pragma unroll
            for (int j = 0; j < 4; j++) acc[i][j] = fmaf(xv[i], wv[j], acc[i][j]);
    }

    #pragma unroll
    for (int i = 0; i < 8; i++) {
        int r = row0 + rb + i;
        if (r < N_NODES) {
            float s = g_dinv[r];
            __half2 h[2];
            h[0] = __floats2half2_rn(acc[i][0] * s, acc[i][1] * s);
            h[1] = __floats2half2_rn(acc[i][2] * s, acc[i][3] * s);
            *(uint2*)(g_hs2h + r * 32 + cb) = *(uint2*)h;
        }
    }
}

// ---------------- agg2: out = dinv*(hs2[n] + sum hs2[src]) + b2 ----------------
// warp per node; 2 sub-warps of 16 lanes alternate edges. Re-zeroes g_cnt/g_base.
__global__ void __launch_bounds__(256) k_agg2(float* __restrict__ out,
                                              const float* __restrict__ b2) {
    int gtid = blockIdx.x * 256 + threadIdx.x;
    if (gtid < N_NODES) g_cnt[gtid] = 0;     // tail-zero for next launch
    if (gtid == 0) g_base = 0;

    int node = blockIdx.x * 8 + (threadIdx.x >> 5);
    if (node >= N_NODES) return;
    int lane = threadIdx.x & 31;
    int sub = lane >> 4;
    int c = lane & 15;
    const __half2* hs = (const __half2*)g_hs2h;

    int start = g_rowptr[node], end = g_rowend[node];
    float2 acc = make_float2(0.f, 0.f);
    if (sub == 0) {
        float2 f = __half22float2(hs[node * 16 + c]);       // self-loop
        acc.x = f.x; acc.y = f.y;
    }
    int e = start + sub;
    for (; e + 2 < end; e += 4) {            // reads e and e+2
        int s0 = g_csrsrc[e], s1 = g_csrsrc[e + 2];
        float2 f0 = __half22float2(hs[s0 * 16 + c]);
        float2 f1 = __half22float2(hs[s1 * 16 + c]);
        acc.x += f0.x + f1.x; acc.y += f0.y + f1.y;
    }
    if (e < end) {
        float2 f = __half22float2(hs[g_csrsrc[e] * 16 + c]);
        acc.x += f.x; acc.y += f.y;
    }
    acc.x += __shfl_xor_sync(0xffffffffu, acc.x, 16);
    acc.y += __shfl_xor_sync(0xffffffffu, acc.y, 16);
    if (sub == 0) {
        float s = g_dinv[node];
        float2 bb = *(const float2*)(b2 + 2 * c);
        float2 o = make_float2(fmaf(acc.x, s, bb.x), fmaf(acc.y, s, bb.y));
        *(float2*)(out + node * 32 + 2 * c) = o;
    }
}

// ---------------- side-stream resources (CPU objects, created once) ----------------
struct SideRes {
    cudaStream_t s;
    cudaEvent_t fork, join;
    SideRes() {
        cudaStreamCreateWithFlags(&s, cudaStreamNonBlocking);
        cudaEventCreateWithFlags(&fork, cudaEventDisableTiming);
        cudaEventCreateWithFlags(&join, cudaEventDisableTiming);
    }
};
static SideRes& side() { static SideRes r; return r; }

// ----------------------------------------------------------------
extern "C" void kernel_launch(void* const* d_in, const int* in_sizes, int n_in,
                              void* d_out, int out_size) {
    const float* x  = (const float*)d_in[0];
    const int*   ei = (const int*)d_in[1];   // int32 (established in R2/R3)
    const float* W1 = (const float*)d_in[2];
    const float* b1 = (const float*)d_in[3];
    const float* W2 = (const float*)d_in[4];
    const float* b2 = (const float*)d_in[5];

    SideRes& r = side();

    k_hist  <<<(N_EDGES / 4 + 255) / 256, 256>>>(ei);
    k_rowptr<<<(N_NODES + 255) / 256, 256>>>();

    // gemm1 needs dinv (epilogue scale) but not the CSR: overlap with permute
    cudaEventRecord(r.fork, (cudaStream_t)0);
    cudaStreamWaitEvent(r.s, r.fork, 0);
    k_gemm1<<<(N_NODES + 127) / 128, 128, 0, r.s>>>(x, W1);
    cudaEventRecord(r.join, r.s);

    k_permute<<<(N_EDGES / 2 + 255) / 256, 256>>>(ei);

    cudaStreamWaitEvent((cudaStream_t)0, r.join, 0);
    k_agg1 <<<(N_NODES + 7) / 8, 256>>>(b1);
    k_gemm2<<<(N_NODES + 127) / 128, 128>>>(W2);
    k_agg2 <<<(N_NODES + 7) / 8, 256>>>((float*)d_out, b2);
}